// round 9
// baseline (speedup 1.0000x reference)
#include <cuda_runtime.h>
#include <cuda_fp16.h>
#include <cstdint>

#define NTH    256
#define KDIM   128
#define TTILE  128
#define ILOOP  4
#define CK_MAX 320
#define GL_MAX 80

// fp16 fragment-packed weights:
// [slot(25)][kc(4)][kb(2)][wn(4)][nq(2)][lane(32)][pos(4)][half(2)]
// slot = etype*3 + rule, slot 24 = loop weight. 8KB per (slot,kc) contiguous.
__device__ __half g_wb[25 * 16384];

__device__ __forceinline__ uint32_t smem_u32(const void* p) {
    uint32_t a;
    asm("{ .reg .u64 t; cvta.to.shared.u64 t, %1; cvt.u32.u64 %0, t; }" : "=r"(a) : "l"(p));
    return a;
}
__device__ __forceinline__ uint32_t pk2(float a, float b) {
    __half2 h = __floats2half2_rn(a, b);
    return *reinterpret_cast<uint32_t*>(&h);
}
__device__ __forceinline__ uint32_t hmul2(uint32_t a, uint32_t b) {
    uint32_t d;
    asm("mul.rn.f16x2 %0, %1, %2;" : "=r"(d) : "r"(a), "r"(b));
    return d;
}

// ---- prep: fragment packing + fp16 rounding of all weights ----
__global__ void prep_w(const float* __restrict__ w, const float* __restrict__ lw) {
    int idx = blockIdx.x * blockDim.x + threadIdx.x;
    if (idx >= 25 * 16384) return;
    int s = idx >> 14, rem = idx & 16383;
    int i = rem >> 7, o = rem & 127;              // B[k=i][n=o]
    float v = (s < 24) ? w[(size_t)s * 16384 + i * 128 + o] : lw[i * 128 + o];
    int kc = i >> 5, kb = (i >> 4) & 1, k16 = i & 15;
    int reg = k16 >> 3, kr = k16 & 7;
    int lane = (o & 7) * 4 + (kr >> 1), hi = kr & 1;
    int wn = o >> 5, ni = (o >> 3) & 3, nq = ni >> 1, pos = (ni & 1) * 2 + reg;
    int flat = s * 16384 + kc * 4096 + kb * 2048 + wn * 512 + nq * 256
             + lane * 8 + pos * 2 + hi;
    g_wb[flat] = __float2half_rn(v);
}

// ---- main: 8 warps (2m x 4n); per-CTA loop over ILOOP t-tiles, one pipeline ----
__global__ __launch_bounds__(NTH, 2)
void rgcn_mma(const float* __restrict__ feat, const float* __restrict__ truth,
              const float* __restrict__ bias,
              const int* __restrict__ src_idx, const int* __restrict__ dst_idx,
              const int* __restrict__ etypes, float* __restrict__ out,
              int N, int T, int E) {
    extern __shared__ char smraw[];
    char*     As  = smraw;                 // 2 x 8KB  (A chunk, 128t x 32k fp16, SW64)
    char*     Bs  = smraw + 16384;         // 2 x 24KB (3 rule B tiles, frag-packed)
    uint32_t* tvs = (uint32_t*)(smraw + 65536);  // 2 x 384 half2-bcast
    int*      ck  = (int*)(tvs + 768);
    int*      gl  = ck + CK_MAX;
    int*      sdst = gl + GL_MAX;

    const int n    = blockIdx.x;
    const int t00  = blockIdx.y * (TTILE * ILOOP);
    const int tid  = threadIdx.x;
    const int lane = tid & 31;
    const int warp = tid >> 5;
    const int wm   = warp >> 2;     // 64-row M half
    const int wn   = warp & 3;      // 32-col N quarter

    // deterministic incident-edge compaction (amortized over ILOOP t-tiles)
    if (tid < E) sdst[tid] = dst_idx[tid];
    __syncthreads();
    if (tid < E && sdst[tid] == n) {
        int pos = 0;
        for (int j = 0; j < tid; j++) pos += (sdst[j] == n);
        gl[pos] = src_idx[tid] | (etypes[tid] << 8) | (tid << 16);
    }
    __syncthreads();
    int ne = 0;
    for (int j = 0; j < E; j++) ne += (sdst[j] == n);
    const int nc = (ne + 1) * 4;    // chunks per t-tile

    // chunk bits: [0:8)=src [8:13)=slot_base [13:15)=kc [15:22)=eid
    for (int i = tid; i < nc; i += NTH) {
        int g = i >> 2, kc = i & 3, v;
        if (g < ne) {
            int e = gl[g];
            v = (e & 0xFF) | ((((e >> 8) & 0xFF) * 3) << 8) | (kc << 13)
              | ((e >> 16) << 15);
        } else {
            v = n | (24 << 8) | (kc << 13);
        }
        ck[i] = v;
    }
    __syncthreads();

    float acc[4][4][4];
#pragma unroll
    for (int mi = 0; mi < 4; mi++)
#pragma unroll
        for (int ni = 0; ni < 4; ni++)
#pragma unroll
            for (int q = 0; q < 4; q++) acc[mi][ni][q] = 0.f;

    const uint32_t As_u = smem_u32(As);
    const uint32_t Bs_u = smem_u32(Bs);

    float  tvf0, tvf1, tvf2;
    float4 fr[4];

    auto a_load = [&](int info, int t0) {
        int src = info & 0xFF, kc = (info >> 13) & 3;
        const float4* fp = (const float4*)(feat + ((size_t)src * T + t0 + (tid >> 1)) * KDIM
                                           + kc * 32 + (tid & 1) * 16);
        fr[0] = fp[0]; fr[1] = fp[1]; fr[2] = fp[2]; fr[3] = fp[3];
        if (((info >> 8) & 0x1F) != 24 && tid < TTILE) {
            const float* tp = truth + ((size_t)((info >> 15) & 0x7F) * T + t0 + tid) * 3;
            tvf0 = tp[0]; tvf1 = tp[1]; tvf2 = tp[2];
        }
    };
    auto b_fill = [&](int info, int buf) {
        int slot = (info >> 8) & 0x1F, kc = (info >> 13) & 3;
        int nr = (slot == 24) ? 1 : 3;
        for (int r = 0; r < nr; r++) {
            const char* gs = (const char*)g_wb + (size_t)(slot + r) * 32768
                           + kc * 8192 + tid * 32;
            uint32_t bd = Bs_u + buf * 24576 + r * 8192 + tid * 32;
            asm volatile("cp.async.cg.shared.global [%0], [%1], 16;" :: "r"(bd), "l"(gs));
            asm volatile("cp.async.cg.shared.global [%0], [%1], 16;" :: "r"(bd + 16), "l"(gs + 16));
        }
    };
    auto a_store = [&](int info, int buf) {
        char* ab = As + buf * 8192;
        uint4 p0, p1;
        p0.x = pk2(fr[0].x, fr[0].y); p0.y = pk2(fr[0].z, fr[0].w);
        p0.z = pk2(fr[1].x, fr[1].y); p0.w = pk2(fr[1].z, fr[1].w);
        p1.x = pk2(fr[2].x, fr[2].y); p1.y = pk2(fr[2].z, fr[2].w);
        p1.z = pk2(fr[3].x, fr[3].y); p1.w = pk2(fr[3].z, fr[3].w);
        uint32_t off0 = (uint32_t)((tid >> 1) * 64 + (tid & 1) * 32);
        uint32_t off1 = off0 + 16;
        *(uint4*)(ab + (off0 ^ ((off0 >> 3) & 0x30))) = p0;
        *(uint4*)(ab + (off1 ^ ((off1 >> 3) & 0x30))) = p1;
        if (((info >> 8) & 0x1F) != 24 && tid < TTILE) {
            uint32_t* tp = tvs + buf * 384;
            tp[tid]       = pk2(tvf0, tvf0);
            tp[128 + tid] = pk2(tvf1, tvf1);
            tp[256 + tid] = pk2(tvf2, tvf2);
        }
    };

    auto comp = [&](int buf, bool selfm) {
        const uint32_t ab_u = As_u + buf * 8192;
        const char* bbase = Bs + buf * 24576;
        const uint32_t* tvp = tvs + buf * 384;
        const int nr = selfm ? 1 : 3;
#pragma unroll
        for (int kb = 0; kb < 2; kb++) {
            uint32_t a[4][4];
#pragma unroll
            for (int mi = 0; mi < 4; mi++) {
                int tl = wm * 64 + mi * 16 + ((lane >> 3) & 1) * 8 + (lane & 7);
                uint32_t off = (uint32_t)(tl * 64 + (kb * 2 + (lane >> 4)) * 16);
                off ^= (off >> 3) & 0x30;
                asm volatile("ldmatrix.sync.aligned.m8n8.x4.shared.b16 {%0,%1,%2,%3}, [%4];"
                    : "=r"(a[mi][0]), "=r"(a[mi][1]), "=r"(a[mi][2]), "=r"(a[mi][3])
                    : "r"(ab_u + off));
            }
#pragma unroll 1
            for (int r = 0; r < nr; r++) {
                const uint4* bp = (const uint4*)(bbase + r * 8192 + kb * 4096 + wn * 1024);
                uint4 bq0 = bp[lane], bq1 = bp[lane + 32];
#pragma unroll
                for (int mi = 0; mi < 4; mi++) {
                    uint32_t am0, am1, am2, am3;
                    if (!selfm) {
                        int row = wm * 64 + mi * 16 + (lane >> 2);
                        uint32_t tlo = tvp[r * 128 + row];
                        uint32_t thi = tvp[r * 128 + row + 8];
                        am0 = hmul2(a[mi][0], tlo); am1 = hmul2(a[mi][1], thi);
                        am2 = hmul2(a[mi][2], tlo); am3 = hmul2(a[mi][3], thi);
                    } else {
                        am0 = a[mi][0]; am1 = a[mi][1]; am2 = a[mi][2]; am3 = a[mi][3];
                    }
#pragma unroll
                    for (int ni = 0; ni < 4; ni++) {
                        uint4 bq = (ni >> 1) ? bq1 : bq0;
                        uint32_t b0 = (ni & 1) ? bq.z : bq.x;
                        uint32_t b1 = (ni & 1) ? bq.w : bq.y;
                        asm volatile(
                            "mma.sync.aligned.m16n8k16.row.col.f32.f16.f16.f32 "
                            "{%0,%1,%2,%3},{%4,%5,%6,%7},{%8,%9},{%0,%1,%2,%3};"
                            : "+f"(acc[mi][ni][0]), "+f"(acc[mi][ni][1]),
                              "+f"(acc[mi][ni][2]), "+f"(acc[mi][ni][3])
                            : "r"(am0), "r"(am1), "r"(am2), "r"(am3),
                              "r"(b0), "r"(b1));
                    }
                }
            }
        }
    };

    auto epilogue = [&](int t0) {
        const int row_base = wm * 64 + (lane >> 2);
        const int col_base = wn * 32 + (lane & 3) * 2;
#pragma unroll
        for (int mi = 0; mi < 4; mi++) {
            float* o0 = out + ((size_t)n * T + t0 + row_base + mi * 16) * KDIM;
#pragma unroll
            for (int ni = 0; ni < 4; ni++) {
                int col = col_base + ni * 8;
                float2 bv = *(const float2*)(bias + col);
                float2 v0 = {acc[mi][ni][0] + bv.x, acc[mi][ni][1] + bv.y};
                float2 v1 = {acc[mi][ni][2] + bv.x, acc[mi][ni][3] + bv.y};
                *(float2*)(o0 + col)            = v0;
                *(float2*)(o0 + 8 * KDIM + col) = v1;
                acc[mi][ni][0] = 0.f; acc[mi][ni][1] = 0.f;
                acc[mi][ni][2] = 0.f; acc[mi][ni][3] = 0.f;
            }
        }
    };

    // ---------------- continuous pipeline across ILOOP t-tiles ----------------
    const int total = nc * ILOOP;
    int info = ck[0];
    b_fill(info, 0);
    a_load(info, t00);
    a_store(info, 0);
    asm volatile("cp.async.commit_group;" ::: "memory");
    asm volatile("cp.async.wait_group 0;" ::: "memory");
    __syncthreads();

    int tt = 0, cc = 0;
    for (int c = 0; c < total; c++) {
        int buf = c & 1;
        bool pre = (c + 1 < total);
        bool selfm = (((ck[cc] >> 8) & 0x1F) == 24);
        int ninfo = 0;
        if (pre) {
            int cc1 = cc + 1, tt1 = tt;
            if (cc1 == nc) { cc1 = 0; tt1++; }
            ninfo = ck[cc1];
            b_fill(ninfo, buf ^ 1);
            a_load(ninfo, t00 + tt1 * TTILE);
        }
        comp(buf, selfm);
        if (pre) a_store(ninfo, buf ^ 1);
        asm volatile("cp.async.commit_group;" ::: "memory");
        asm volatile("cp.async.wait_group 0;" ::: "memory");
        __syncthreads();
        if (++cc == nc) {               // t-tile finished: write + reset acc
            epilogue(t00 + tt * TTILE);
            cc = 0; tt++;
        }
    }
}

// ---------------- launch ----------------
extern "C" void kernel_launch(void* const* d_in, const int* in_sizes, int n_in,
                              void* d_out, int out_size) {
    const float* feat   = (const float*)d_in[0];
    const float* truth  = (const float*)d_in[1];
    const float* weight = (const float*)d_in[2];
    const float* loop_w = (const float*)d_in[3];
    const float* bias   = (const float*)d_in[4];
    const int*   src    = (const int*)d_in[5];
    const int*   dst    = (const int*)d_in[6];
    const int*   etyp   = (const int*)d_in[7];
    float*       out    = (float*)d_out;

    const int E = in_sizes[5];
    const int T = in_sizes[1] / (E * 3);
    const int N = in_sizes[0] / (T * KDIM);

    prep_w<<<(25 * 16384 + 255) / 256, 256>>>(weight, loop_w);

    size_t smem = 65536 + 768 * 4 + (size_t)(CK_MAX + GL_MAX + GL_MAX) * 4;
    cudaFuncSetAttribute(rgcn_mma, cudaFuncAttributeMaxDynamicSharedMemorySize, (int)smem);
    dim3 grid(N, T / (TTILE * ILOOP));
    rgcn_mma<<<grid, NTH, smem>>>(feat, truth, bias, src, dst, etyp, out, N, T, E);
}

// round 10
// speedup vs baseline: 1.1635x; 1.1635x over previous
#include <cuda_runtime.h>
#include <cuda_fp16.h>
#include <cstdint>

#define NTH    256
#define KDIM   128
#define TTILE  128

// fp16 fragment-packed weights:
// [slot(25)][kc(4)][kb(2)][wn(4)][nq(2)][lane(32)][pos(4)][half(2)]
// slot = etype*3 + rule, slot 24 = loop weight. 8KB per (slot,kc) contiguous.
__device__ __half g_wb[25 * 16384];

__device__ __forceinline__ uint32_t smem_u32(const void* p) {
    uint32_t a;
    asm("{ .reg .u64 t; cvta.to.shared.u64 t, %1; cvt.u32.u64 %0, t; }" : "=r"(a) : "l"(p));
    return a;
}
__device__ __forceinline__ uint32_t pk2(float a, float b) {
    __half2 h = __floats2half2_rn(a, b);
    return *reinterpret_cast<uint32_t*>(&h);
}
__device__ __forceinline__ uint32_t hmul2(uint32_t a, uint32_t b) {
    uint32_t d;
    asm("mul.rn.f16x2 %0, %1, %2;" : "=r"(d) : "r"(a), "r"(b));
    return d;
}

// ---- prep: fragment packing + fp16 rounding of all weights ----
__global__ void prep_w(const float* __restrict__ w, const float* __restrict__ lw) {
    int idx = blockIdx.x * blockDim.x + threadIdx.x;
    if (idx >= 25 * 16384) return;
    int s = idx >> 14, rem = idx & 16383;
    int i = rem >> 7, o = rem & 127;              // B[k=i][n=o]
    float v = (s < 24) ? w[(size_t)s * 16384 + i * 128 + o] : lw[i * 128 + o];
    int kc = i >> 5, kb = (i >> 4) & 1, k16 = i & 15;
    int reg = k16 >> 3, kr = k16 & 7;
    int lane = (o & 7) * 4 + (kr >> 1), hi = kr & 1;
    int wn = o >> 5, ni = (o >> 3) & 3, nq = ni >> 1, pos = (ni & 1) * 2 + reg;
    int flat = s * 16384 + kc * 4096 + kb * 2048 + wn * 512 + nq * 256
             + lane * 8 + pos * 2 + hi;
    g_wb[flat] = __float2half_rn(v);
}

// ============================ kernel 1: self loop ============================
// out[n, t0.., :] = bias + feat[n, t0..,:] @ loop_w     (uniform, 1 GEMM/CTA)
__global__ __launch_bounds__(NTH, 2)
void rgcn_self(const float* __restrict__ feat, const float* __restrict__ bias,
               float* __restrict__ out, int T) {
    extern __shared__ char smraw[];
    char* As = smraw;               // 2 x 8KB
    char* Bs = smraw + 16384;       // 2 x 8KB

    const int n    = blockIdx.x;
    const int t0   = blockIdx.y * TTILE;
    const int tid  = threadIdx.x;
    const int lane = tid & 31;
    const int warp = tid >> 5;
    const int wm   = warp >> 2;
    const int wn   = warp & 3;

    float acc[4][4][4];
#pragma unroll
    for (int mi = 0; mi < 4; mi++)
#pragma unroll
        for (int ni = 0; ni < 4; ni++)
#pragma unroll
            for (int q = 0; q < 4; q++) acc[mi][ni][q] = 0.f;

    const uint32_t As_u = smem_u32(As);
    const uint32_t Bs_u = smem_u32(Bs);
    float4 fr[4];

    auto a_load = [&](int kc) {
        const float4* fp = (const float4*)(feat + ((size_t)n * T + t0 + (tid >> 1)) * KDIM
                                           + kc * 32 + (tid & 1) * 16);
        fr[0] = fp[0]; fr[1] = fp[1]; fr[2] = fp[2]; fr[3] = fp[3];
    };
    auto b_fill = [&](int kc, int buf) {
        const char* gs = (const char*)g_wb + (size_t)24 * 32768 + kc * 8192 + tid * 32;
        uint32_t bd = Bs_u + buf * 8192 + tid * 32;
        asm volatile("cp.async.cg.shared.global [%0], [%1], 16;" :: "r"(bd), "l"(gs));
        asm volatile("cp.async.cg.shared.global [%0], [%1], 16;" :: "r"(bd + 16), "l"(gs + 16));
    };
    auto a_store = [&](int buf) {
        char* ab = As + buf * 8192;
        uint4 p0, p1;
        p0.x = pk2(fr[0].x, fr[0].y); p0.y = pk2(fr[0].z, fr[0].w);
        p0.z = pk2(fr[1].x, fr[1].y); p0.w = pk2(fr[1].z, fr[1].w);
        p1.x = pk2(fr[2].x, fr[2].y); p1.y = pk2(fr[2].z, fr[2].w);
        p1.z = pk2(fr[3].x, fr[3].y); p1.w = pk2(fr[3].z, fr[3].w);
        uint32_t off0 = (uint32_t)((tid >> 1) * 64 + (tid & 1) * 32);
        uint32_t off1 = off0 + 16;
        *(uint4*)(ab + (off0 ^ ((off0 >> 3) & 0x30))) = p0;
        *(uint4*)(ab + (off1 ^ ((off1 >> 3) & 0x30))) = p1;
    };
    auto comp = [&](int buf) {
        const uint32_t ab_u = As_u + buf * 8192;
        const char* bbase = Bs + buf * 8192;
#pragma unroll
        for (int kb = 0; kb < 2; kb++) {
            uint32_t a[4][4];
#pragma unroll
            for (int mi = 0; mi < 4; mi++) {
                int tl = wm * 64 + mi * 16 + ((lane >> 3) & 1) * 8 + (lane & 7);
                uint32_t off = (uint32_t)(tl * 64 + (kb * 2 + (lane >> 4)) * 16);
                off ^= (off >> 3) & 0x30;
                asm volatile("ldmatrix.sync.aligned.m8n8.x4.shared.b16 {%0,%1,%2,%3}, [%4];"
                    : "=r"(a[mi][0]), "=r"(a[mi][1]), "=r"(a[mi][2]), "=r"(a[mi][3])
                    : "r"(ab_u + off));
            }
            const uint4* bp = (const uint4*)(bbase + kb * 4096 + wn * 1024);
            uint4 bq0 = bp[lane], bq1 = bp[lane + 32];
#pragma unroll
            for (int mi = 0; mi < 4; mi++)
#pragma unroll
                for (int ni = 0; ni < 4; ni++) {
                    uint4 bq = (ni >> 1) ? bq1 : bq0;
                    uint32_t b0 = (ni & 1) ? bq.z : bq.x;
                    uint32_t b1 = (ni & 1) ? bq.w : bq.y;
                    asm volatile(
                        "mma.sync.aligned.m16n8k16.row.col.f32.f16.f16.f32 "
                        "{%0,%1,%2,%3},{%4,%5,%6,%7},{%8,%9},{%0,%1,%2,%3};"
                        : "+f"(acc[mi][ni][0]), "+f"(acc[mi][ni][1]),
                          "+f"(acc[mi][ni][2]), "+f"(acc[mi][ni][3])
                        : "r"(a[mi][0]), "r"(a[mi][1]), "r"(a[mi][2]), "r"(a[mi][3]),
                          "r"(b0), "r"(b1));
                }
        }
    };

    b_fill(0, 0);
    a_load(0);
    a_store(0);
    asm volatile("cp.async.commit_group;" ::: "memory");
    asm volatile("cp.async.wait_group 0;" ::: "memory");
    __syncthreads();
    for (int c = 0; c < 4; c++) {
        int buf = c & 1;
        if (c < 3) { b_fill(c + 1, buf ^ 1); a_load(c + 1); }
        comp(buf);
        if (c < 3) a_store(buf ^ 1);
        asm volatile("cp.async.commit_group;" ::: "memory");
        asm volatile("cp.async.wait_group 0;" ::: "memory");
        __syncthreads();
    }

    const int row_base = wm * 64 + (lane >> 2);
    const int col_base = wn * 32 + (lane & 3) * 2;
#pragma unroll
    for (int mi = 0; mi < 4; mi++) {
        float* o0 = out + ((size_t)n * T + t0 + row_base + mi * 16) * KDIM;
#pragma unroll
        for (int ni = 0; ni < 4; ni++) {
            int col = col_base + ni * 8;
            float2 bv = *(const float2*)(bias + col);
            float2 v0 = {acc[mi][ni][0] + bv.x, acc[mi][ni][1] + bv.y};
            float2 v1 = {acc[mi][ni][2] + bv.x, acc[mi][ni][3] + bv.y};
            *(float2*)(o0 + col)            = v0;
            *(float2*)(o0 + 8 * KDIM + col) = v1;
        }
    }
}

// ============================ kernel 2: edges ============================
// Uniform: CTA = (edge, t-tile): 3 tv-scaled GEMMs, RED-accumulate to out[dst].
__global__ __launch_bounds__(NTH, 2)
void rgcn_edge(const float* __restrict__ feat, const float* __restrict__ truth,
               const int* __restrict__ src_idx, const int* __restrict__ dst_idx,
               const int* __restrict__ etypes, float* __restrict__ out, int T) {
    extern __shared__ char smraw[];
    char*     As  = smraw;                 // 2 x 8KB
    char*     Bs  = smraw + 16384;         // 2 x 24KB
    uint32_t* tvs = (uint32_t*)(smraw + 65536);  // 3 x 128 half2-bcast

    const int e    = blockIdx.x;
    const int t0   = blockIdx.y * TTILE;
    const int tid  = threadIdx.x;
    const int lane = tid & 31;
    const int warp = tid >> 5;
    const int wm   = warp >> 2;
    const int wn   = warp & 3;

    const int src  = src_idx[e];
    const int dstn = dst_idx[e];
    const int slot = etypes[e] * 3;

    // tv for this t-tile: load once, broadcast pairs
    if (tid < TTILE) {
        const float* tp = truth + ((size_t)e * T + t0 + tid) * 3;
        tvs[tid]       = pk2(tp[0], tp[0]);
        tvs[128 + tid] = pk2(tp[1], tp[1]);
        tvs[256 + tid] = pk2(tp[2], tp[2]);
    }

    float acc[4][4][4];
#pragma unroll
    for (int mi = 0; mi < 4; mi++)
#pragma unroll
        for (int ni = 0; ni < 4; ni++)
#pragma unroll
            for (int q = 0; q < 4; q++) acc[mi][ni][q] = 0.f;

    const uint32_t As_u = smem_u32(As);
    const uint32_t Bs_u = smem_u32(Bs);
    float4 fr[4];

    auto a_load = [&](int kc) {
        const float4* fp = (const float4*)(feat + ((size_t)src * T + t0 + (tid >> 1)) * KDIM
                                           + kc * 32 + (tid & 1) * 16);
        fr[0] = fp[0]; fr[1] = fp[1]; fr[2] = fp[2]; fr[3] = fp[3];
    };
    auto b_fill = [&](int kc, int buf) {
#pragma unroll
        for (int r = 0; r < 3; r++) {
            const char* gs = (const char*)g_wb + (size_t)(slot + r) * 32768
                           + kc * 8192 + tid * 32;
            uint32_t bd = Bs_u + buf * 24576 + r * 8192 + tid * 32;
            asm volatile("cp.async.cg.shared.global [%0], [%1], 16;" :: "r"(bd), "l"(gs));
            asm volatile("cp.async.cg.shared.global [%0], [%1], 16;" :: "r"(bd + 16), "l"(gs + 16));
        }
    };
    auto a_store = [&](int buf) {
        char* ab = As + buf * 8192;
        uint4 p0, p1;
        p0.x = pk2(fr[0].x, fr[0].y); p0.y = pk2(fr[0].z, fr[0].w);
        p0.z = pk2(fr[1].x, fr[1].y); p0.w = pk2(fr[1].z, fr[1].w);
        p1.x = pk2(fr[2].x, fr[2].y); p1.y = pk2(fr[2].z, fr[2].w);
        p1.z = pk2(fr[3].x, fr[3].y); p1.w = pk2(fr[3].z, fr[3].w);
        uint32_t off0 = (uint32_t)((tid >> 1) * 64 + (tid & 1) * 32);
        uint32_t off1 = off0 + 16;
        *(uint4*)(ab + (off0 ^ ((off0 >> 3) & 0x30))) = p0;
        *(uint4*)(ab + (off1 ^ ((off1 >> 3) & 0x30))) = p1;
    };
    auto comp = [&](int buf) {
        const uint32_t ab_u = As_u + buf * 8192;
        const char* bbase = Bs + buf * 24576;
#pragma unroll
        for (int kb = 0; kb < 2; kb++) {
            uint32_t a[4][4];
#pragma unroll
            for (int mi = 0; mi < 4; mi++) {
                int tl = wm * 64 + mi * 16 + ((lane >> 3) & 1) * 8 + (lane & 7);
                uint32_t off = (uint32_t)(tl * 64 + (kb * 2 + (lane >> 4)) * 16);
                off ^= (off >> 3) & 0x30;
                asm volatile("ldmatrix.sync.aligned.m8n8.x4.shared.b16 {%0,%1,%2,%3}, [%4];"
                    : "=r"(a[mi][0]), "=r"(a[mi][1]), "=r"(a[mi][2]), "=r"(a[mi][3])
                    : "r"(ab_u + off));
            }
#pragma unroll 1
            for (int r = 0; r < 3; r++) {
                const uint4* bp = (const uint4*)(bbase + r * 8192 + kb * 4096 + wn * 1024);
                uint4 bq0 = bp[lane], bq1 = bp[lane + 32];
#pragma unroll
                for (int mi = 0; mi < 4; mi++) {
                    int row = wm * 64 + mi * 16 + (lane >> 2);
                    uint32_t tlo = tvs[r * 128 + row];
                    uint32_t thi = tvs[r * 128 + row + 8];
                    uint32_t am0 = hmul2(a[mi][0], tlo), am1 = hmul2(a[mi][1], thi);
                    uint32_t am2 = hmul2(a[mi][2], tlo), am3 = hmul2(a[mi][3], thi);
#pragma unroll
                    for (int ni = 0; ni < 4; ni++) {
                        uint4 bq = (ni >> 1) ? bq1 : bq0;
                        uint32_t b0 = (ni & 1) ? bq.z : bq.x;
                        uint32_t b1 = (ni & 1) ? bq.w : bq.y;
                        asm volatile(
                            "mma.sync.aligned.m16n8k16.row.col.f32.f16.f16.f32 "
                            "{%0,%1,%2,%3},{%4,%5,%6,%7},{%8,%9},{%0,%1,%2,%3};"
                            : "+f"(acc[mi][ni][0]), "+f"(acc[mi][ni][1]),
                              "+f"(acc[mi][ni][2]), "+f"(acc[mi][ni][3])
                            : "r"(am0), "r"(am1), "r"(am2), "r"(am3),
                              "r"(b0), "r"(b1));
                    }
                }
            }
        }
    };

    b_fill(0, 0);
    a_load(0);
    a_store(0);
    asm volatile("cp.async.commit_group;" ::: "memory");
    asm volatile("cp.async.wait_group 0;" ::: "memory");
    __syncthreads();
    for (int c = 0; c < 4; c++) {
        int buf = c & 1;
        if (c < 3) { b_fill(c + 1, buf ^ 1); a_load(c + 1); }
        comp(buf);
        if (c < 3) a_store(buf ^ 1);
        asm volatile("cp.async.commit_group;" ::: "memory");
        asm volatile("cp.async.wait_group 0;" ::: "memory");
        __syncthreads();
    }

    // RED-accumulate message tile into out[dst]
    const int row_base = wm * 64 + (lane >> 2);
    const int col_base = wn * 32 + (lane & 3) * 2;
#pragma unroll
    for (int mi = 0; mi < 4; mi++) {
        float* o0 = out + ((size_t)dstn * T + t0 + row_base + mi * 16) * KDIM;
#pragma unroll
        for (int ni = 0; ni < 4; ni++) {
            int col = col_base + ni * 8;
            asm volatile("red.global.add.v2.f32 [%0], {%1,%2};"
                         :: "l"(o0 + col), "f"(acc[mi][ni][0]), "f"(acc[mi][ni][1]) : "memory");
            asm volatile("red.global.add.v2.f32 [%0], {%1,%2};"
                         :: "l"(o0 + 8 * KDIM + col), "f"(acc[mi][ni][2]), "f"(acc[mi][ni][3]) : "memory");
        }
    }
}

// ---------------- launch ----------------
extern "C" void kernel_launch(void* const* d_in, const int* in_sizes, int n_in,
                              void* d_out, int out_size) {
    const float* feat   = (const float*)d_in[0];
    const float* truth  = (const float*)d_in[1];
    const float* weight = (const float*)d_in[2];
    const float* loop_w = (const float*)d_in[3];
    const float* bias   = (const float*)d_in[4];
    const int*   src    = (const int*)d_in[5];
    const int*   dst    = (const int*)d_in[6];
    const int*   etyp   = (const int*)d_in[7];
    float*       out    = (float*)d_out;

    const int E = in_sizes[5];
    const int T = in_sizes[1] / (E * 3);
    const int N = in_sizes[0] / (T * KDIM);

    prep_w<<<(25 * 16384 + 255) / 256, 256>>>(weight, loop_w);

    size_t smem_s = 32768;
    cudaFuncSetAttribute(rgcn_self, cudaFuncAttributeMaxDynamicSharedMemorySize, (int)smem_s);
    rgcn_self<<<dim3(N, T / TTILE), NTH, smem_s>>>(feat, bias, out, T);

    size_t smem_e = 65536 + 384 * 4;
    cudaFuncSetAttribute(rgcn_edge, cudaFuncAttributeMaxDynamicSharedMemorySize, (int)smem_e);
    rgcn_edge<<<dim3(E, T / TTILE), NTH, smem_e>>>(feat, truth, src, dst, etyp, out, T);
}